// round 3
// baseline (speedup 1.0000x reference)
#include <cuda_runtime.h>
#include <math.h>

#define B_   2
#define S_   512
#define T_   1024        // B*S tokens
#define D_   1280
#define H_   20
#define DK_  64
#define L_   16
#define DI_  2560        // D_INNER
#define W1O_ 5120
#define VOC_ 1024
#define NP_  10
#define OUT_PER_B (VOC_*S_*NP_)   // 5242880

// ---------------- scratch (device globals; no allocation) ----------------
// layout in floats:
//  x:      0          (1,310,720)
//  h:      1,310,720
//  q:      2,621,440
//  k:      3,932,160
//  v:      5,242,880
//  o:      6,553,600
//  u:      7,864,320  (5,242,880)
//  gate:  13,107,200  (2,621,440)
//  scores:15,728,640  (10,485,760)
#define OFF_X  0
#define OFF_H  1310720
#define OFF_Q  2621440
#define OFF_K  3932160
#define OFF_V  5242880
#define OFF_O  6553600
#define OFF_U  7864320
#define OFF_G  13107200
#define OFF_S  15728640
__device__ float g_scratch[26214400];

// ---------------- embedding: x[t,d] = emb_b[d] + sum_c lat[b,c,n]*emb_w[d,c] -
__global__ void embed_kernel(const float* __restrict__ latents,
                             const float* __restrict__ emb_w,
                             const float* __restrict__ emb_b,
                             float* __restrict__ x) {
    int t = blockIdx.y;
    int d = blockIdx.x * 256 + threadIdx.x;
    __shared__ float lat[112];
    int b = t >> 9, n = t & 511;
    if (threadIdx.x < 112)
        lat[threadIdx.x] = latents[(size_t)b * 57344 + threadIdx.x * 512 + n];
    __syncthreads();
    float s = emb_b[d];
    const float* wrow = emb_w + (size_t)d * 112;
#pragma unroll 8
    for (int c = 0; c < 112; c++) s += lat[c] * wrow[c];
    x[(size_t)t * D_ + d] = s;
}

// ---------------- rmsnorm: one block per token ----------------
__global__ __launch_bounds__(256) void rmsnorm_kernel(const float* __restrict__ x,
                                                      const float* __restrict__ w,
                                                      float* __restrict__ out) {
    int t = blockIdx.x;
    const float* xr = x + (size_t)t * D_;
    float ss = 0.f;
    for (int i = threadIdx.x; i < D_; i += 256) { float v = xr[i]; ss += v * v; }
    __shared__ float red[8];
    float v = ss;
#pragma unroll
    for (int off = 16; off; off >>= 1) v += __shfl_down_sync(0xffffffffu, v, off);
    if ((threadIdx.x & 31) == 0) red[threadIdx.x >> 5] = v;
    __syncthreads();
    if (threadIdx.x == 0) {
        float r = 0.f;
#pragma unroll
        for (int i = 0; i < 8; i++) r += red[i];
        red[0] = r;
    }
    __syncthreads();
    float inv = 1.0f / sqrtf(red[0] / (float)D_ + 1e-5f);
    float* orow = out + (size_t)t * D_;
    for (int i = threadIdx.x; i < D_; i += 256) orow[i] = w[i] * (xr[i] * inv);
}

// ---------------- generic SGEMM NN: C[M,N] (+)= A[M,K] @ B[K,N] ----------------
// tiles: 64(M) x 128(N) x 16(K); 256 threads; 4x8 microtile
template <bool ACC>
__global__ __launch_bounds__(256) void sgemm_nn(const float* __restrict__ A,
                                                const float* __restrict__ Bm,
                                                float* __restrict__ C,
                                                int N, int K) {
    __shared__ float As[16][64];
    __shared__ float Bs[16][128];
    const int tid = threadIdx.x;
    const int m0 = blockIdx.y * 64;
    const int n0 = blockIdx.x * 128;
    const int a_row = tid >> 2, a_c4 = (tid & 3) << 2;
    const int b_row = tid >> 5, b_c4 = (tid & 31) << 2;
    const int tx = tid & 15, ty = tid >> 4;
    const float* Aptr = A + (size_t)(m0 + a_row) * K + a_c4;
    const float* Bptr = Bm + (size_t)b_row * N + n0 + b_c4;

    float acc[4][8];
#pragma unroll
    for (int i = 0; i < 4; i++)
#pragma unroll
        for (int j = 0; j < 8; j++) acc[i][j] = 0.f;

    for (int k0 = 0; k0 < K; k0 += 16) {
        float4 av  = *(const float4*)(Aptr + k0);
        float4 bv0 = *(const float4*)(Bptr + (size_t)k0 * N);
        float4 bv1 = *(const float4*)(Bptr + (size_t)(k0 + 8) * N);
        __syncthreads();
        As[a_c4 + 0][a_row] = av.x;
        As[a_c4 + 1][a_row] = av.y;
        As[a_c4 + 2][a_row] = av.z;
        As[a_c4 + 3][a_row] = av.w;
        *(float4*)&Bs[b_row][b_c4]     = bv0;
        *(float4*)&Bs[b_row + 8][b_c4] = bv1;
        __syncthreads();
#pragma unroll
        for (int kk = 0; kk < 16; kk++) {
            float4 a  = *(const float4*)&As[kk][ty * 4];
            float4 b0 = *(const float4*)&Bs[kk][tx * 8];
            float4 b1 = *(const float4*)&Bs[kk][tx * 8 + 4];
            float af[4] = {a.x, a.y, a.z, a.w};
            float bf[8] = {b0.x, b0.y, b0.z, b0.w, b1.x, b1.y, b1.z, b1.w};
#pragma unroll
            for (int i = 0; i < 4; i++)
#pragma unroll
                for (int j = 0; j < 8; j++) acc[i][j] += af[i] * bf[j];
        }
    }
#pragma unroll
    for (int i = 0; i < 4; i++) {
        float* cp = C + (size_t)(m0 + ty * 4 + i) * N + n0 + tx * 8;
        if (ACC) {
            float4 c0 = *(float4*)cp, c1 = *(float4*)(cp + 4);
            c0.x += acc[i][0]; c0.y += acc[i][1]; c0.z += acc[i][2]; c0.w += acc[i][3];
            c1.x += acc[i][4]; c1.y += acc[i][5]; c1.z += acc[i][6]; c1.w += acc[i][7];
            *(float4*)cp = c0; *(float4*)(cp + 4) = c1;
        } else {
            float4 c0 = {acc[i][0], acc[i][1], acc[i][2], acc[i][3]};
            float4 c1 = {acc[i][4], acc[i][5], acc[i][6], acc[i][7]};
            *(float4*)cp = c0; *(float4*)(cp + 4) = c1;
        }
    }
}

// ---------------- attention scores: scores[bh,i,j] = q.k/8 (+bias layer0) ------
__global__ __launch_bounds__(256) void attn_scores_kernel(const float* __restrict__ q,
                                                          const float* __restrict__ k,
                                                          const float* __restrict__ rel_bias,
                                                          float* __restrict__ scores,
                                                          int add_bias) {
    __shared__ float Qs[64][68];  // [dim][row]
    __shared__ float Ks[64][68];
    int tid = threadIdx.x;
    int bh = blockIdx.z, b = bh / H_, h = bh - b * H_;
    int i0 = blockIdx.y * 64, j0 = blockIdx.x * 64;
    const float* qbase = q + (size_t)(b * S_) * D_ + h * DK_;
    const float* kbase = k + (size_t)(b * S_) * D_ + h * DK_;
#pragma unroll
    for (int l = 0; l < 4; l++) {
        int idx = tid + l * 256;
        int row = idx >> 4;
        int c4 = (idx & 15) << 2;
        float4 vq = *(const float4*)(qbase + (size_t)(i0 + row) * D_ + c4);
        Qs[c4][row] = vq.x; Qs[c4 + 1][row] = vq.y; Qs[c4 + 2][row] = vq.z; Qs[c4 + 3][row] = vq.w;
        float4 vk = *(const float4*)(kbase + (size_t)(j0 + row) * D_ + c4);
        Ks[c4][row] = vk.x; Ks[c4 + 1][row] = vk.y; Ks[c4 + 2][row] = vk.z; Ks[c4 + 3][row] = vk.w;
    }
    __syncthreads();
    int tx = tid & 15, ty = tid >> 4;
    float acc[4][4];
#pragma unroll
    for (int i = 0; i < 4; i++)
#pragma unroll
        for (int j = 0; j < 4; j++) acc[i][j] = 0.f;
#pragma unroll 8
    for (int kk = 0; kk < 64; kk++) {
        float4 a = *(const float4*)&Qs[kk][ty * 4];
        float4 bq = *(const float4*)&Ks[kk][tx * 4];
        float af[4] = {a.x, a.y, a.z, a.w};
        float bf[4] = {bq.x, bq.y, bq.z, bq.w};
#pragma unroll
        for (int i = 0; i < 4; i++)
#pragma unroll
            for (int j = 0; j < 4; j++) acc[i][j] += af[i] * bf[j];
    }
#pragma unroll
    for (int ii = 0; ii < 4; ii++) {
        int i = i0 + ty * 4 + ii;
#pragma unroll
        for (int jj = 0; jj < 4; jj++) {
            int j = j0 + tx * 4 + jj;
            float s = acc[ii][jj] * 0.125f;
            if (add_bias) {
                int n = i - j;
                int ret = (n < 0) ? 16 : 0;
                int an = (n < 0) ? -n : n;
                int val;
                if (an < 8) val = an;
                else {
                    val = 8 + (int)(logf((float)an / 8.0f) / logf(16.0f) * 8.0f);
                    if (val > 15) val = 15;
                }
                s += rel_bias[(ret + val) * H_ + h];
            }
            scores[(size_t)(bh * S_ + i) * S_ + j] = s;
        }
    }
}

// ---------------- softmax over last dim (512) ----------------
__global__ __launch_bounds__(256) void softmax_kernel(float* __restrict__ scores) {
    size_t row = blockIdx.x;
    float* p = scores + row * S_;
    int tid = threadIdx.x;
    float v0 = p[tid], v1 = p[tid + 256];
    float m = fmaxf(v0, v1);
    __shared__ float redm[8];
    __shared__ float reds[8];
#pragma unroll
    for (int off = 16; off; off >>= 1) m = fmaxf(m, __shfl_down_sync(0xffffffffu, m, off));
    if ((tid & 31) == 0) redm[tid >> 5] = m;
    __syncthreads();
    if (tid == 0) {
        float mm = redm[0];
#pragma unroll
        for (int i = 1; i < 8; i++) mm = fmaxf(mm, redm[i]);
        redm[0] = mm;
    }
    __syncthreads();
    float bm = redm[0];
    float e0 = expf(v0 - bm), e1 = expf(v1 - bm);
    float s = e0 + e1;
#pragma unroll
    for (int off = 16; off; off >>= 1) s += __shfl_down_sync(0xffffffffu, s, off);
    if ((tid & 31) == 0) reds[tid >> 5] = s;
    __syncthreads();
    if (tid == 0) {
        float t = 0.f;
#pragma unroll
        for (int i = 0; i < 8; i++) t += reds[i];
        reds[0] = t;
    }
    __syncthreads();
    float inv = 1.0f / reds[0];
    p[tid] = e0 * inv;
    p[tid + 256] = e1 * inv;
}

// ---------------- o = attn @ v  (per b,h: 512x64x512) ----------------
__global__ __launch_bounds__(256) void attn_av_kernel(const float* __restrict__ attn,
                                                      const float* __restrict__ v,
                                                      float* __restrict__ o) {
    __shared__ float As[32][68];  // [k][m]
    __shared__ float Vs[32][64];  // [k][n]
    int tid = threadIdx.x;
    int bh = blockIdx.y, b = bh / H_, h = bh - b * H_;
    int i0 = blockIdx.x * 64;
    const float* abase = attn + (size_t)bh * S_ * S_;
    const float* vbase = v + (size_t)(b * S_) * D_ + h * DK_;
    int tx = tid & 15, ty = tid >> 4;
    float acc[4][4];
#pragma unroll
    for (int i = 0; i < 4; i++)
#pragma unroll
        for (int j = 0; j < 4; j++) acc[i][j] = 0.f;

    for (int k0 = 0; k0 < S_; k0 += 32) {
        __syncthreads();
#pragma unroll
        for (int l = 0; l < 2; l++) {
            int idx = tid + l * 256;
            int row = idx >> 3;
            int c4 = (idx & 7) << 2;
            float4 a = *(const float4*)(abase + (size_t)(i0 + row) * S_ + k0 + c4);
            As[c4][row] = a.x; As[c4 + 1][row] = a.y; As[c4 + 2][row] = a.z; As[c4 + 3][row] = a.w;
            int vr = idx >> 4;
            int vc4 = (idx & 15) << 2;
            *(float4*)&Vs[vr][vc4] = *(const float4*)(vbase + (size_t)(k0 + vr) * D_ + vc4);
        }
        __syncthreads();
#pragma unroll 8
        for (int kk = 0; kk < 32; kk++) {
            float4 a = *(const float4*)&As[kk][ty * 4];
            float4 bv = *(const float4*)&Vs[kk][tx * 4];
            float af[4] = {a.x, a.y, a.z, a.w};
            float bf[4] = {bv.x, bv.y, bv.z, bv.w};
#pragma unroll
            for (int i = 0; i < 4; i++)
#pragma unroll
                for (int j = 0; j < 4; j++) acc[i][j] += af[i] * bf[j];
        }
    }
#pragma unroll
    for (int ii = 0; ii < 4; ii++) {
        float4 c = {acc[ii][0], acc[ii][1], acc[ii][2], acc[ii][3]};
        *(float4*)(o + (size_t)(b * S_ + i0 + ty * 4 + ii) * D_ + h * DK_ + tx * 4) = c;
    }
}

// ---------------- GEGLU: gate[t,j] = u[t,j] * gelu(u[t,2560+j]) ----------------
__global__ void geglu_kernel(const float* __restrict__ u, float* __restrict__ g) {
    int idx = blockIdx.x * 256 + threadIdx.x;   // over T_*DI_
    int t = idx / DI_, j = idx - t * DI_;
    float a = u[(size_t)t * W1O_ + j];
    float gg = u[(size_t)t * W1O_ + DI_ + j];
    float g3 = gg * gg * gg;
    float th = tanhf(0.7978845608028654f * (gg + 0.044715f * g3));
    g[idx] = a * (0.5f * gg * (1.0f + th));
}

// ---------------- classifier: out scatter of X @ W^T + b ----------------
// A: [1024,1280] (normed x), W: [10240,1280], bias [10240]
// out[b, v, s*10+p] = sum_d A[(b,s),d]*W[v*10+p,d] + bias[v*10+p]
__global__ __launch_bounds__(256) void classifier_kernel(const float* __restrict__ A,
                                                         const float* __restrict__ W,
                                                         const float* __restrict__ bias,
                                                         float* __restrict__ out) {
    __shared__ float As[16][64];
    __shared__ float Bs[16][132];
    const int tid = threadIdx.x;
    const int m0 = blockIdx.y * 64;
    const int n0 = blockIdx.x * 128;
    const int a_row = tid >> 2, a_c4 = (tid & 3) << 2;
    const int tx = tid & 15, ty = tid >> 4;
    const int K = D_;
    float acc[4][8];
#pragma unroll
    for (int i = 0; i < 4; i++)
#pragma unroll
        for (int j = 0; j < 8; j++) acc[i][j] = 0.f;

    for (int k0 = 0; k0 < K; k0 += 16) {
        float4 av = *(const float4*)(A + (size_t)(m0 + a_row) * K + k0 + a_c4);
        float4 bv[2];
#pragma unroll
        for (int l = 0; l < 2; l++) {
            int idx = tid + l * 256;
            int row = idx >> 2;
            int c4 = (idx & 3) << 2;
            bv[l] = *(const float4*)(W + (size_t)(n0 + row) * K + k0 + c4);
        }
        __syncthreads();
        As[a_c4 + 0][a_row] = av.x;
        As[a_c4 + 1][a_row] = av.y;
        As[a_c4 + 2][a_row] = av.z;
        As[a_c4 + 3][a_row] = av.w;
#pragma unroll
        for (int l = 0; l < 2; l++) {
            int idx = tid + l * 256;
            int row = idx >> 2;
            int c4 = (idx & 3) << 2;
            Bs[c4 + 0][row] = bv[l].x;
            Bs[c4 + 1][row] = bv[l].y;
            Bs[c4 + 2][row] = bv[l].z;
            Bs[c4 + 3][row] = bv[l].w;
        }
        __syncthreads();
#pragma unroll
        for (int kk = 0; kk < 16; kk++) {
            float4 a  = *(const float4*)&As[kk][ty * 4];
            float4 b0 = *(const float4*)&Bs[kk][tx * 8];
            float4 b1 = *(const float4*)&Bs[kk][tx * 8 + 4];
            float af[4] = {a.x, a.y, a.z, a.w};
            float bf[8] = {b0.x, b0.y, b0.z, b0.w, b1.x, b1.y, b1.z, b1.w};
#pragma unroll
            for (int i = 0; i < 4; i++)
#pragma unroll
                for (int j = 0; j < 8; j++) acc[i][j] += af[i] * bf[j];
        }
    }
#pragma unroll
    for (int ii = 0; ii < 4; ii++) {
        int t = m0 + ty * 4 + ii;
        int bb = t >> 9, s = t & 511;
#pragma unroll
        for (int jj = 0; jj < 8; jj++) {
            int oidx = n0 + tx * 8 + jj;
            int vv = oidx / NP_;
            int pp = oidx - vv * NP_;
            out[(size_t)bb * OUT_PER_B + (size_t)vv * (S_ * NP_) + s * NP_ + pp] =
                acc[ii][jj] + bias[oidx];
        }
    }
}

// ---------------- host launch ----------------
extern "C" void kernel_launch(void* const* d_in, const int* in_sizes, int n_in,
                              void* d_out, int out_size) {
    const float* latents    = (const float*)d_in[0];
    const float* emb_w      = (const float*)d_in[1];
    const float* emb_b      = (const float*)d_in[2];
    const float* norm_w     = (const float*)d_in[3];
    const float* wq         = (const float*)d_in[4];
    const float* wk         = (const float*)d_in[5];
    const float* wv         = (const float*)d_in[6];
    const float* wo         = (const float*)d_in[7];
    const float* w1         = (const float*)d_in[8];
    const float* w2         = (const float*)d_in[9];
    const float* rel_bias   = (const float*)d_in[10];
    const float* norm_out_w = (const float*)d_in[11];
    const float* cls_w      = (const float*)d_in[12];
    const float* cls_b      = (const float*)d_in[13];
    float* out = (float*)d_out;

    float* ws = nullptr;
    cudaGetSymbolAddress((void**)&ws, g_scratch);
    float* x      = ws + OFF_X;
    float* h      = ws + OFF_H;
    float* q      = ws + OFF_Q;
    float* k      = ws + OFF_K;
    float* v      = ws + OFF_V;
    float* o      = ws + OFF_O;
    float* u      = ws + OFF_U;
    float* gate   = ws + OFF_G;
    float* scores = ws + OFF_S;

    // embedding
    embed_kernel<<<dim3(D_ / 256, T_), 256>>>(latents, emb_w, emb_b, x);

    const dim3 gD(D_ / 128, T_ / 64);      // N=1280 gemms
    const dim3 gW1(W1O_ / 128, T_ / 64);   // N=5120
    const dim3 gSc(S_ / 64, S_ / 64, B_ * H_);
    const dim3 gAv(S_ / 64, B_ * H_);

    for (int l = 0; l < L_; l++) {
        const float* nw  = norm_w + (size_t)l * D_;
        const float* wql = wq + (size_t)l * D_ * D_;
        const float* wkl = wk + (size_t)l * D_ * D_;
        const float* wvl = wv + (size_t)l * D_ * D_;
        const float* wol = wo + (size_t)l * D_ * D_;
        const float* w1l = w1 + (size_t)l * D_ * W1O_;
        const float* w2l = w2 + (size_t)l * DI_ * D_;

        rmsnorm_kernel<<<T_, 256>>>(x, nw, h);
        sgemm_nn<false><<<gD, 256>>>(h, wql, q, D_, D_);
        sgemm_nn<false><<<gD, 256>>>(h, wkl, k, D_, D_);
        sgemm_nn<false><<<gD, 256>>>(h, wvl, v, D_, D_);
        attn_scores_kernel<<<gSc, 256>>>(q, k, rel_bias, scores, l == 0 ? 1 : 0);
        softmax_kernel<<<B_ * H_ * S_, 256>>>(scores);
        attn_av_kernel<<<gAv, 256>>>(scores, v, o);
        sgemm_nn<true><<<gD, 256>>>(o, wol, x, D_, D_);
        sgemm_nn<false><<<gW1, 256>>>(x, w1l, u, W1O_, D_);
        geglu_kernel<<<(T_ * DI_) / 256, 256>>>(u, gate);
        sgemm_nn<true><<<gD, 256>>>(gate, w2l, x, D_, DI_);
    }

    rmsnorm_kernel<<<T_, 256>>>(x, norm_out_w, h);
    classifier_kernel<<<dim3((VOC_ * NP_) / 128, T_ / 64), 256>>>(h, cls_w, cls_b, out);
}

// round 5
// speedup vs baseline: 3.8629x; 3.8629x over previous
#include <cuda_runtime.h>
#include <cuda_bf16.h>
#include <math.h>
#include <stdint.h>

typedef __nv_bfloat16 bf16;

#define B_   2
#define S_   512
#define T_   1024
#define D_   1280
#define H_   20
#define L_   16
#define DI_  2560
#define W1O_ 5120
#define OUT_PER_B 5242880

// ---------------- PTX helpers (baseline, non-'a' features only) ----------------
__device__ __forceinline__ uint32_t smem_u32(const void* p) {
    uint32_t a;
    asm("{ .reg .u64 t; cvta.to.shared.u64 t, %1; cvt.u32.u64 %0, t; }" : "=r"(a) : "l"(p));
    return a;
}
#define SWZ(o) ((o) ^ (((o) >> 3) & 0x70))

#define CPASYNC(dst, src) \
    asm volatile("cp.async.cg.shared.global [%0], [%1], 16;" :: "r"(dst), "l"(src))
#define CPCOMMIT() asm volatile("cp.async.commit_group;" ::: "memory")
#define CPWAIT1()  asm volatile("cp.async.wait_group 1;" ::: "memory")
#define CPWAIT0()  asm volatile("cp.async.wait_group 0;" ::: "memory")

__device__ __forceinline__ void ldsm4(uint32_t* r, uint32_t addr) {
    asm volatile("ldmatrix.sync.aligned.m8n8.x4.shared.b16 {%0,%1,%2,%3}, [%4];"
        : "=r"(r[0]), "=r"(r[1]), "=r"(r[2]), "=r"(r[3]) : "r"(addr));
}
__device__ __forceinline__ uint32_t lds32(uint32_t addr) {
    uint32_t v;
    asm volatile("ld.shared.b32 %0, [%1];" : "=r"(v) : "r"(addr));
    return v;
}
__device__ __forceinline__ void mma_bf16(float* d, const uint32_t* a, const uint32_t* b) {
    asm volatile(
        "mma.sync.aligned.m16n8k16.row.col.f32.bf16.bf16.f32 "
        "{%0,%1,%2,%3}, {%4,%5,%6,%7}, {%8,%9}, {%0,%1,%2,%3};"
        : "+f"(d[0]), "+f"(d[1]), "+f"(d[2]), "+f"(d[3])
        : "r"(a[0]), "r"(a[1]), "r"(a[2]), "r"(a[3]), "r"(b[0]), "r"(b[1]));
}

// ---------------- scratch (bf16 arena) ----------------
#define O_QKVT_H 0ll
#define O_QKVT_L 78643200ll
#define O_WOT_H  157286400ll
#define O_WOT_L  183500800ll
#define O_W1T_H  209715200ll
#define O_W1T_L  314572800ll
#define O_W2T_H  419430400ll
#define O_W2T_L  471859200ll
#define O_CLST_H 524288000ll
#define O_CLST_L 537395200ll
#define O_H_H    550502400ll
#define O_H_L    551813120ll
#define O_QKV_H  553123840ll
#define O_QKV_L  557056000ll
#define O_VT_H   560988160ll  /* 40*64*512 + 32768 pad */
#define O_VT_L   562331648ll
#define O_ATT_H  563675136ll
#define O_ATT_L  574160896ll
#define O_O_H    584646656ll
#define O_O_L    585957376ll
#define O_XS_H   587268096ll
#define O_XS_L   588578816ll
#define O_G_H    589889536ll
#define O_G_L    592510976ll
__device__ bf16 g_bf[595132416ll];
#define OF_X 0
#define OF_U 1310720
#define OF_S 6553600
__device__ float g_f[17039360];

// ---------------- small kernels ----------------
__global__ void embed_kernel(const float* __restrict__ lat, const float* __restrict__ ew,
                             const float* __restrict__ eb, float* __restrict__ x) {
    int t = blockIdx.y, d = blockIdx.x * 256 + threadIdx.x;
    __shared__ float l[112];
    int b = t >> 9, n = t & 511;
    if (threadIdx.x < 112) l[threadIdx.x] = lat[(size_t)b * 57344 + threadIdx.x * 512 + n];
    __syncthreads();
    float s = eb[d];
    const float* w = ew + (size_t)d * 112;
#pragma unroll 8
    for (int c = 0; c < 112; c++) s += l[c] * w[c];
    x[(size_t)t * D_ + d] = s;
}

__device__ __forceinline__ void spst(float v, bf16* hi, bf16* lo, size_t i) {
    bf16 h = __float2bfloat16(v);
    hi[i] = h;
    lo[i] = __float2bfloat16(v - __bfloat162float(h));
}

__global__ __launch_bounds__(256) void rmsnorm_kernel(const float* __restrict__ x,
                                                      const float* __restrict__ w,
                                                      bf16* __restrict__ oh, bf16* __restrict__ ol) {
    int t = blockIdx.x;
    const float* xr = x + (size_t)t * D_;
    float ss = 0.f;
    for (int i = threadIdx.x; i < D_; i += 256) { float v = xr[i]; ss += v * v; }
    __shared__ float red[8];
    float v = ss;
#pragma unroll
    for (int o = 16; o; o >>= 1) v += __shfl_down_sync(~0u, v, o);
    if ((threadIdx.x & 31) == 0) red[threadIdx.x >> 5] = v;
    __syncthreads();
    if (threadIdx.x == 0) { float r = 0.f; for (int i = 0; i < 8; i++) r += red[i]; red[0] = r; }
    __syncthreads();
    float inv = rsqrtf(red[0] / (float)D_ + 1e-5f);
    size_t b = (size_t)t * D_;
    for (int i = threadIdx.x; i < D_; i += 256) spst(w[i] * (xr[i] * inv), oh, ol, b + i);
}

__device__ __forceinline__ float relbias(const float* __restrict__ rb, int i, int j, int h) {
    int n = i - j, ret = (n < 0) ? 16 : 0, an = (n < 0) ? -n : n, val;
    if (an < 8) val = an;
    else { val = 8 + (int)(logf((float)an * 0.125f) * (8.0f / logf(16.0f))); if (val > 15) val = 15; }
    return rb[(ret + val) * H_ + h];
}

__global__ __launch_bounds__(256) void softmax_kernel(const float* __restrict__ sc,
                                                      const float* __restrict__ rb,
                                                      bf16* __restrict__ ah, bf16* __restrict__ al,
                                                      int add_bias) {
    int i = blockIdx.x, bh = blockIdx.y, h = bh % H_, tid = threadIdx.x;
    const float* p = sc + ((size_t)bh * S_ + i) * S_;
    float v0 = p[tid], v1 = p[tid + 256];
    if (add_bias) { v0 += relbias(rb, i, tid, h); v1 += relbias(rb, i, tid + 256, h); }
    float m = fmaxf(v0, v1);
    __shared__ float rm[8], rs[8];
#pragma unroll
    for (int o = 16; o; o >>= 1) m = fmaxf(m, __shfl_down_sync(~0u, m, o));
    if ((tid & 31) == 0) rm[tid >> 5] = m;
    __syncthreads();
    if (tid == 0) { float mm = rm[0]; for (int k = 1; k < 8; k++) mm = fmaxf(mm, rm[k]); rm[0] = mm; }
    __syncthreads();
    float bm = rm[0], e0 = expf(v0 - bm), e1 = expf(v1 - bm), s = e0 + e1;
#pragma unroll
    for (int o = 16; o; o >>= 1) s += __shfl_down_sync(~0u, s, o);
    if ((tid & 31) == 0) rs[tid >> 5] = s;
    __syncthreads();
    if (tid == 0) { float t = 0.f; for (int k = 0; k < 8; k++) t += rs[k]; rs[0] = t; }
    __syncthreads();
    float inv = 1.0f / rs[0];
    size_t ob = ((size_t)bh * S_ + i) * S_;
    spst(e0 * inv, ah, al, ob + tid);
    spst(e1 * inv, ah, al, ob + tid + 256);
}

__global__ void geglu_kernel(const float* __restrict__ u, bf16* __restrict__ gh, bf16* __restrict__ gl) {
    int idx = blockIdx.x * 256 + threadIdx.x;
    int t = idx / DI_, j = idx - t * DI_;
    float a = u[(size_t)t * W1O_ + j];
    float g = u[(size_t)t * W1O_ + DI_ + j];
    float th = tanhf(0.7978845608028654f * (g + 0.044715f * g * g * g));
    spst(a * (0.5f * g * (1.0f + th)), gh, gl, idx);
}

__global__ void split_kernel(const float* __restrict__ s, bf16* __restrict__ hi, bf16* __restrict__ lo) {
    int i = (blockIdx.x * 256 + threadIdx.x) << 2;
    float4 v = *(const float4*)(s + i);
    spst(v.x, hi, lo, i); spst(v.y, hi, lo, i + 1);
    spst(v.z, hi, lo, i + 2); spst(v.w, hi, lo, i + 3);
}

// transpose+split: src fp32 [K][N] (z-batched) -> dst bf16 [N][K]
__global__ __launch_bounds__(256) void trans_split(const float* __restrict__ src, long long sZ,
                                                   int K, int N,
                                                   bf16* __restrict__ dh, bf16* __restrict__ dl,
                                                   long long dZ) {
    __shared__ float t[32][33];
    int c = threadIdx.x & 31, r0 = threadIdx.x >> 5;
    int n0 = blockIdx.x * 32, k0 = blockIdx.y * 32;
    const float* s = src + (size_t)blockIdx.z * sZ;
#pragma unroll
    for (int i = 0; i < 4; i++) { int r = r0 + i * 8; t[r][c] = s[(size_t)(k0 + r) * N + n0 + c]; }
    __syncthreads();
    size_t db = (size_t)blockIdx.z * dZ;
#pragma unroll
    for (int i = 0; i < 4; i++) {
        int n = r0 + i * 8;
        spst(t[c][n], dh, dl, db + (size_t)(n0 + n) * K + k0 + c);
    }
}

// v transpose: qkv split [t][3840] (v at col 2560+h*64) -> vt[bh][64][512]
__global__ __launch_bounds__(256) void vtrans_kernel(const bf16* __restrict__ vh, const bf16* __restrict__ vl,
                                                     bf16* __restrict__ th_, bf16* __restrict__ tl_) {
    __shared__ bf16 th[32][72], tl[32][72];
    int tid = threadIdx.x, bh = blockIdx.y, b = bh / H_, h = bh - b * H_;
    int s0 = blockIdx.x * 32;
    size_t sb = (size_t)(b * S_ + s0) * 3840 + 2560 + h * 64;
    int r = tid >> 3, c8 = (tid & 7) * 8;
    *(uint4*)&th[r][c8] = *(const uint4*)(vh + sb + (size_t)r * 3840 + c8);
    *(uint4*)&tl[r][c8] = *(const uint4*)(vl + sb + (size_t)r * 3840 + c8);
    __syncthreads();
    int dk = tid >> 2, s4 = (tid & 3) * 8;
    bf16 oh[8], ol[8];
#pragma unroll
    for (int i = 0; i < 8; i++) { oh[i] = th[s4 + i][dk]; ol[i] = tl[s4 + i][dk]; }
    size_t db = ((size_t)bh * 64 + dk) * 512 + s0 + s4;
    *(uint4*)(th_ + db) = *(uint4*)oh;
    *(uint4*)(tl_ + db) = *(uint4*)ol;
}

// ---------------- split-bf16 HMMA GEMM (mma.sync m16n8k16) ----------------
// CTA tile 128x128, K-block 64, 8 warps (2m x 4n), warp tile 64x32.
// SMEM per stage: Ah|Al|Bh|Bl each [128][64] bf16 (SW128 swizzled) = 64KB; 2 stages.
// EPI: 0 = f32*alpha store, 1 = split bf16 store, 2 = f32 residual +=, 3 = classifier scatter
template <int EPI>
__global__ __launch_bounds__(256, 1) void hgemm(
    const bf16* __restrict__ Ah, const bf16* __restrict__ Al, long long lda, long long aS1, long long aS2,
    const bf16* __restrict__ Bh, const bf16* __restrict__ Bl, long long ldb, long long bS1, long long bS2,
    int K, int zdiv, int nvalid, float alpha,
    float* __restrict__ Cf, bf16* __restrict__ Ch, bf16* __restrict__ Cl,
    long long ldc, long long cS1, long long cS2, const float* __restrict__ bias) {
    extern __shared__ char sm[];
    const int tid = threadIdx.x, lane = tid & 31, wid = tid >> 5;
    const int wm = wid & 1, wn = wid >> 1;
    const int zq = blockIdx.z / zdiv, zr = blockIdx.z - zq * zdiv;
    const int m0 = blockIdx.y * 128, n0 = blockIdx.x * 128;
    const bf16* Ahp = Ah + zq * aS1 + zr * aS2 + (size_t)m0 * lda;
    const bf16* Alp = Al + zq * aS1 + zr * aS2 + (size_t)m0 * lda;
    const bf16* Bhp = Bh + zq * bS1 + zr * bS2 + (size_t)n0 * ldb;
    const bf16* Blp = Bl + zq * bS1 + zr * bS2 + (size_t)n0 * ldb;
    const uint32_t sbase = smem_u32(sm);
    const int KB = K >> 6;

    float acc[4][4][4];
#pragma unroll
    for (int a = 0; a < 4; a++)
#pragma unroll
        for (int b = 0; b < 4; b++)
#pragma unroll
            for (int c = 0; c < 4; c++) acc[a][b][c] = 0.f;

    // thread's load slots (4 iters x 4 tiles)
    const int lr = tid >> 3, lc = tid & 7;  // base row/col16 for i=0

#define LOAD_STAGE(st, kb) do { \
    uint32_t bse = sbase + (st) * 65536; \
    long long ko = (long long)(kb) * 64; \
    _Pragma("unroll") \
    for (int i = 0; i < 4; i++) { \
        int r = lr + i * 32; \
        uint32_t so = SWZ(r * 128 + lc * 16); \
        CPASYNC(bse + so,         Ahp + (size_t)r * lda + ko + lc * 8); \
        CPASYNC(bse + 16384 + so, Alp + (size_t)r * lda + ko + lc * 8); \
        CPASYNC(bse + 32768 + so, Bhp + (size_t)r * ldb + ko + lc * 8); \
        CPASYNC(bse + 49152 + so, Blp + (size_t)r * ldb + ko + lc * 8); \
    } \
    CPCOMMIT(); \
} while (0)

    LOAD_STAGE(0, 0);
    if (KB > 1) LOAD_STAGE(1, 1);

    const int g = lane >> 2, t4 = lane & 3;
    const int arow = wm * 64 + (lane & 15);
    const int acolb = (lane >> 4) * 16;

    for (int kb = 0; kb < KB; kb++) {
        if (kb + 2 <= KB) CPWAIT1(); else CPWAIT0();
        __syncthreads();
        uint32_t sAh = sbase + (kb & 1) * 65536;
        uint32_t sAl = sAh + 16384, sBh = sAh + 32768, sBl = sAh + 49152;
#pragma unroll
        for (int ks = 0; ks < 4; ks++) {
            uint32_t aH[4][4], aL[4][4], bH[4][2], bL[4][2];
#pragma unroll
            for (int mi = 0; mi < 4; mi++) {
                uint32_t off = SWZ((arow + mi * 16) * 128 + ks * 32 + acolb);
                ldsm4(aH[mi], sAh + off);
                ldsm4(aL[mi], sAl + off);
            }
#pragma unroll
            for (int ni = 0; ni < 4; ni++) {
                int row = wn * 32 + ni * 8 + g;
                uint32_t o0 = SWZ(row * 128 + ks * 32 + t4 * 4);
                uint32_t o1 = SWZ(row * 128 + ks * 32 + t4 * 4 + 16);
                bH[ni][0] = lds32(sBh + o0); bH[ni][1] = lds32(sBh + o1);
                bL[ni][0] = lds32(sBl + o0); bL[ni][1] = lds32(sBl + o1);
            }
#pragma unroll
            for (int mi = 0; mi < 4; mi++)
#pragma unroll
                for (int ni = 0; ni < 4; ni++) {
                    mma_bf16(acc[mi][ni], aH[mi], bH[ni]);
                    mma_bf16(acc[mi][ni], aH[mi], bL[ni]);
                    mma_bf16(acc[mi][ni], aL[mi], bH[ni]);
                }
        }
        __syncthreads();
        if (kb + 2 < KB) LOAD_STAGE(kb & 1, kb + 2);
    }
#undef LOAD_STAGE

    // epilogue
    const long long coff = zq * cS1 + zr * cS2;
#pragma unroll
    for (int mi = 0; mi < 4; mi++) {
        int r0 = m0 + wm * 64 + mi * 16 + g;
        int r1 = r0 + 8;
#pragma unroll
        for (int ni = 0; ni < 4; ni++) {
            int col = n0 + wn * 32 + ni * 8 + t4 * 2;
            if (col >= nvalid) continue;
            float v0 = acc[mi][ni][0], v1 = acc[mi][ni][1];
            float v2 = acc[mi][ni][2], v3 = acc[mi][ni][3];
            if (EPI == 0) {
                float2 p0 = {v0 * alpha, v1 * alpha}, p1 = {v2 * alpha, v3 * alpha};
                *(float2*)(Cf + coff + (size_t)r0 * ldc + col) = p0;
                *(float2*)(Cf + coff + (size_t)r1 * ldc + col) = p1;
            } else if (EPI == 1) {
                size_t i0 = coff + (size_t)r0 * ldc + col;
                size_t i1 = coff + (size_t)r1 * ldc + col;
                bf16 h0 = __float2bfloat16(v0), h1 = __float2bfloat16(v1);
                bf16 h2 = __float2bfloat16(v2), h3 = __float2bfloat16(v3);
                __nv_bfloat162 hh0; hh0.x = h0; hh0.y = h1;
                __nv_bfloat162 hh1; hh1.x = h2; hh1.y = h3;
                *(__nv_bfloat162*)(Ch + i0) = hh0;
                *(__nv_bfloat162*)(Ch + i1) = hh1;
                __nv_bfloat162 ll0, ll1;
                ll0.x = __float2bfloat16(v0 - __bfloat162float(h0));
                ll0.y = __float2bfloat16(v1 - __bfloat162float(h1));
                ll1.x = __float2bfloat16(v2 - __bfloat162float(h2));
                ll1.y = __float2bfloat16(v3 - __bfloat162float(h3));
                *(__nv_bfloat162*)(Cl + i0) = ll0;
                *(__nv_bfloat162*)(Cl + i1) = ll1;
            } else if (EPI == 2) {
                float* p0 = Cf + coff + (size_t)r0 * ldc + col;
                float* p1 = Cf + coff + (size_t)r1 * ldc + col;
                float2 c0 = *(float2*)p0, c1 = *(float2*)p1;
                c0.x += v0; c0.y += v1; c1.x += v2; c1.y += v3;
                *(float2*)p0 = c0; *(float2*)p1 = c1;
            } else {
                int b0 = r0 >> 9, s0 = r0 & 511, b1 = r1 >> 9, s1 = r1 & 511;
#pragma unroll
                for (int e = 0; e < 2; e++) {
                    int cc = col + e;
                    int vv = cc / 10, pp = cc - vv * 10;
                    float bv = bias[cc];
                    Cf[(size_t)b0 * OUT_PER_B + (size_t)vv * 5120 + s0 * 10 + pp] = (e ? v1 : v0) + bv;
                    Cf[(size_t)b1 * OUT_PER_B + (size_t)vv * 5120 + s1 * 10 + pp] = (e ? v3 : v2) + bv;
                }
            }
        }
    }
}

// ---------------- host ----------------
extern "C" void kernel_launch(void* const* d_in, const int* in_sizes, int n_in,
                              void* d_out, int out_size) {
    const float* latents  = (const float*)d_in[0];
    const float* emb_w    = (const float*)d_in[1];
    const float* emb_b    = (const float*)d_in[2];
    const float* norm_w   = (const float*)d_in[3];
    const float* wq       = (const float*)d_in[4];
    const float* wk       = (const float*)d_in[5];
    const float* wv       = (const float*)d_in[6];
    const float* wo       = (const float*)d_in[7];
    const float* w1       = (const float*)d_in[8];
    const float* w2       = (const float*)d_in[9];
    const float* rel_bias = (const float*)d_in[10];
    const float* now      = (const float*)d_in[11];
    const float* cls_w    = (const float*)d_in[12];
    const float* cls_b    = (const float*)d_in[13];
    float* out = (float*)d_out;

    bf16* bfp = nullptr; float* fp = nullptr;
    cudaGetSymbolAddress((void**)&bfp, g_bf);
    cudaGetSymbolAddress((void**)&fp, g_f);

    const int SMEM = 131072;
    cudaFuncSetAttribute(hgemm<0>, cudaFuncAttributeMaxDynamicSharedMemorySize, SMEM);
    cudaFuncSetAttribute(hgemm<1>, cudaFuncAttributeMaxDynamicSharedMemorySize, SMEM);
    cudaFuncSetAttribute(hgemm<2>, cudaFuncAttributeMaxDynamicSharedMemorySize, SMEM);
    cudaFuncSetAttribute(hgemm<3>, cudaFuncAttributeMaxDynamicSharedMemorySize, SMEM);

    float* x  = fp + OF_X;
    float* u  = fp + OF_U;
    float* sc = fp + OF_S;

    // weight prep: transpose [K][N] -> [N][K] + split hi/lo
    trans_split<<<dim3(40, 40, 16), 256>>>(wq, 1638400, 1280, 1280, bfp + O_QKVT_H,           bfp + O_QKVT_L,           4915200);
    trans_split<<<dim3(40, 40, 16), 256>>>(wk, 1638400, 1280, 1280, bfp + O_QKVT_H + 1638400, bfp + O_QKVT_L + 1638400, 4915200);
    trans_split<<<dim3(40, 40, 16), 256>>>(wv, 1638400, 1280, 1280, bfp + O_QKVT_H + 3276800, bfp + O_QKVT_L + 3276800, 4915200);
    trans_split<<<dim3(40, 40, 16), 256>>>(wo, 1638400, 1280, 1280, bfp + O_WOT_H, bfp + O_WOT_L, 1638400);
    trans_split<<<dim3(160, 40, 16), 256>>>(w1, 6553600, 1280, 5120, bfp + O_W1T_H, bfp + O_W1T_L, 6553600);
    trans_split<<<dim3(40, 80, 16), 256>>>(w2, 3276800, 2560, 1280, bfp + O_W2T_H, bfp + O_W2T_L, 3276800);
    split_kernel<<<12800, 256>>>(cls_w, bfp + O_CLST_H, bfp + O_CLST_L);

    embed_kernel<<<dim3(5, 1024), 256>>>(latents, emb_w, emb_b, x);

    for (int l = 0; l < L_; l++) {
        rmsnorm_kernel<<<T_, 256>>>(x, norm_w + (size_t)l * D_, bfp + O_H_H, bfp + O_H_L);
        // QKV: [1024,1280] @ [3840,1280]^T -> split qkv
        hgemm<1><<<dim3(30, 8, 1), 256, SMEM>>>(
            bfp + O_H_H, bfp + O_H_L, 1280, 0, 0,
            bfp + O_QKVT_H + (size_t)l * 4915200, bfp + O_QKVT_L + (size_t)l * 4915200, 1280, 0, 0,
            1280, 1, 3840, 1.f, nullptr, bfp + O_QKV_H, bfp + O_QKV_L, 3840, 0, 0, nullptr);
        vtrans_kernel<<<dim3(16, 40), 256>>>(bfp + O_QKV_H, bfp + O_QKV_L, bfp + O_VT_H, bfp + O_VT_L);
        // scores: per bh q[512,64] @ k[512,64]^T * 0.125 -> f32
        hgemm<0><<<dim3(4, 4, 40), 256, SMEM>>>(
            bfp + O_QKV_H, bfp + O_QKV_L, 3840, 1966080, 64,
            bfp + O_QKV_H + 1280, bfp + O_QKV_L + 1280, 3840, 1966080, 64,
            64, 20, 512, 0.125f, sc, nullptr, nullptr, 512, 5242880, 262144, nullptr);
        softmax_kernel<<<dim3(512, 40), 256>>>(sc, rel_bias, bfp + O_ATT_H, bfp + O_ATT_L, l == 0 ? 1 : 0);
        // AV: att[512,512] @ vt[64,512]^T -> o split (cols h*64..h*64+63)
        hgemm<1><<<dim3(1, 4, 40), 256, SMEM>>>(
            bfp + O_ATT_H, bfp + O_ATT_L, 512, 5242880, 262144,
            bfp + O_VT_H, bfp + O_VT_L, 512, 655360, 32768,
            512, 20, 64, 1.f, nullptr, bfp + O_O_H, bfp + O_O_L, 1280, 655360, 64, nullptr);
        // x += o @ woT
        hgemm<2><<<dim3(10, 8, 1), 256, SMEM>>>(
            bfp + O_O_H, bfp + O_O_L, 1280, 0, 0,
            bfp + O_WOT_H + (size_t)l * 1638400, bfp + O_WOT_L + (size_t)l * 1638400, 1280, 0, 0,
            1280, 1, 1280, 1.f, x, nullptr, nullptr, 1280, 0, 0, nullptr);
        split_kernel<<<1280, 256>>>(x, bfp + O_XS_H, bfp + O_XS_L);
        // u = x @ w1T -> f32
        hgemm<0><<<dim3(40, 8, 1), 256, SMEM>>>(
            bfp + O_XS_H, bfp + O_XS_L, 1280, 0, 0,
            bfp + O_W1T_H + (size_t)l * 6553600, bfp + O_W1T_L + (size_t)l * 6553600, 1280, 0, 0,
            1280, 1, 5120, 1.f, u, nullptr, nullptr, 5120, 0, 0, nullptr);
        geglu_kernel<<<(T_ * DI_) / 256, 256>>>(u, bfp + O_G_H, bfp + O_G_L);
        // x += g @ w2T
        hgemm<2><<<dim3(10, 8, 1), 256, SMEM>>>(
            bfp + O_G_H, bfp + O_G_L, 2560, 0, 0,
            bfp + O_W2T_H + (size_t)l * 3276800, bfp + O_W2T_L + (size_t)l * 3276800, 2560, 0, 0,
            2560, 1, 1280, 1.f, x, nullptr, nullptr, 1280, 0, 0, nullptr);
    }

    rmsnorm_kernel<<<T_, 256>>>(x, now, bfp + O_H_H, bfp + O_H_L);
    hgemm<3><<<dim3(80, 8, 1), 256, SMEM>>>(
        bfp + O_H_H, bfp + O_H_L, 1280, 0, 0,
        bfp + O_CLST_H, bfp + O_CLST_L, 1280, 0, 0,
        1280, 1, 10240, 1.f, out, nullptr, nullptr, 0, 0, 0, cls_b);
}